// round 5
// baseline (speedup 1.0000x reference)
#include <cuda_runtime.h>
#include <cuda_bf16.h>
#include <math.h>
#include <cstdint>

constexpr int HD = 1024;
constexpr int NH = 8;
constexpr int DH = 128;
constexpr int BB = 4;
constexpr int TT = 2048;
constexpr int MM = BB * TT; // 8192

typedef unsigned long long ull;

// ---- scratch (allocation-free) ----
__device__ __nv_bfloat16 g_xn2[MM * 2048];           // LN out [hi|lo]
__device__ __nv_bfloat16 g_w2[4][1024 * 2048];       // weights split [hi|lo]
__device__ __nv_bfloat16 g_q2[32 * TT * 256];        // [B*NH][T][hi128|lo128], pre-scaled
__device__ __nv_bfloat16 g_k2[32 * TT * 256];
__device__ __nv_bfloat16 g_v2[32 * TT * 256];
__device__ __nv_bfloat16 g_attn2[MM * 2048];         // attn split [hi|lo]

// ============================================================
// helpers
// ============================================================
__device__ __forceinline__ uint32_t s2u(const void* p) {
    uint32_t a;
    asm("{ .reg .u64 t; cvta.to.shared.u64 t, %1; cvt.u32.u64 %0, t; }" : "=r"(a) : "l"(p));
    return a;
}
__device__ __forceinline__ void cpasync16(uint32_t smem, const void* g) {
    asm volatile("cp.async.cg.shared.global [%0], [%1], 16;" :: "r"(smem), "l"(g));
}
__device__ __forceinline__ void cpcommit() { asm volatile("cp.async.commit_group;" ::: "memory"); }
template<int N> __device__ __forceinline__ void cpwait() {
    asm volatile("cp.async.wait_group %0;" :: "n"(N) : "memory");
}
__device__ __forceinline__ void ldsm4(uint32_t* r, uint32_t addr) {
    asm volatile("ldmatrix.sync.aligned.m8n8.x4.shared.b16 {%0,%1,%2,%3}, [%4];"
                 : "=r"(r[0]), "=r"(r[1]), "=r"(r[2]), "=r"(r[3]) : "r"(addr));
}
__device__ __forceinline__ void ldsm4t(uint32_t* r, uint32_t addr) {
    asm volatile("ldmatrix.sync.aligned.m8n8.x4.trans.shared.b16 {%0,%1,%2,%3}, [%4];"
                 : "=r"(r[0]), "=r"(r[1]), "=r"(r[2]), "=r"(r[3]) : "r"(addr));
}
__device__ __forceinline__ void mma16816(float* d, const uint32_t* a, uint32_t b0, uint32_t b1) {
    asm volatile("mma.sync.aligned.m16n8k16.row.col.f32.bf16.bf16.f32 "
                 "{%0,%1,%2,%3}, {%4,%5,%6,%7}, {%8,%9}, {%0,%1,%2,%3};"
                 : "+f"(d[0]), "+f"(d[1]), "+f"(d[2]), "+f"(d[3])
                 : "r"(a[0]), "r"(a[1]), "r"(a[2]), "r"(a[3]), "r"(b0), "r"(b1));
}
__device__ __forceinline__ void split_bf16(float x, __nv_bfloat16 &h, __nv_bfloat16 &l) {
    h = __float2bfloat16_rn(x);
    l = __float2bfloat16_rn(x - __bfloat162float(h));
}
__device__ __forceinline__ uint32_t pack_split_hi(float a, float b) {
    __nv_bfloat16 ha, la, hb, lb;
    split_bf16(a, ha, la); split_bf16(b, hb, lb);
    return (uint32_t)__bfloat16_as_ushort(ha) | ((uint32_t)__bfloat16_as_ushort(hb) << 16);
}
__device__ __forceinline__ void pack_split2(float a, float b, uint32_t &hi, uint32_t &lo) {
    __nv_bfloat16 ha, la, hb, lb;
    split_bf16(a, ha, la); split_bf16(b, hb, lb);
    hi = (uint32_t)__bfloat16_as_ushort(ha) | ((uint32_t)__bfloat16_as_ushort(hb) << 16);
    lo = (uint32_t)__bfloat16_as_ushort(la) | ((uint32_t)__bfloat16_as_ushort(lb) << 16);
}

// ============================================================
// LayerNorm -> bf16 hi/lo split [row][2048]
// ============================================================
__global__ void __launch_bounds__(256) ln_kernel(
    const float* __restrict__ x, const float* __restrict__ gamma,
    const float* __restrict__ beta, __nv_bfloat16* __restrict__ xn2)
{
    int row = blockIdx.x;
    int tid = threadIdx.x;
    const float* xr = x + (size_t)row * HD;
    float4 v = *(const float4*)&xr[tid * 4];
    float s  = v.x + v.y + v.z + v.w;
    float ss = v.x * v.x + v.y * v.y + v.z * v.z + v.w * v.w;
    #pragma unroll
    for (int o = 16; o; o >>= 1) {
        s  += __shfl_xor_sync(0xffffffffu, s,  o);
        ss += __shfl_xor_sync(0xffffffffu, ss, o);
    }
    __shared__ float rs[8], rss[8];
    if ((tid & 31) == 0) { rs[tid >> 5] = s; rss[tid >> 5] = ss; }
    __syncthreads();
    s = 0.f; ss = 0.f;
    #pragma unroll
    for (int i = 0; i < 8; i++) { s += rs[i]; ss += rss[i]; }
    float mu  = s * (1.0f / HD);
    float inv = rsqrtf(ss * (1.0f / HD) - mu * mu + 1e-5f);
    float4 g  = *(const float4*)&gamma[tid * 4];
    float4 be = *(const float4*)&beta[tid * 4];
    float o[4];
    o[0] = (v.x - mu) * inv * g.x + be.x;
    o[1] = (v.y - mu) * inv * g.y + be.y;
    o[2] = (v.z - mu) * inv * g.z + be.z;
    o[3] = (v.w - mu) * inv * g.w + be.w;
    __nv_bfloat16 hi[4], lo[4];
    #pragma unroll
    for (int i = 0; i < 4; i++) split_bf16(o[i], hi[i], lo[i]);
    *(ull*)&xn2[(size_t)row * 2048 + tid * 4]        = *(ull*)hi;
    *(ull*)&xn2[(size_t)row * 2048 + 1024 + tid * 4] = *(ull*)lo;
}

// fp32 -> bf16 hi/lo split (weights)
__global__ void __launch_bounds__(256) conv_split(
    const float* __restrict__ A, __nv_bfloat16* __restrict__ A2)
{
    int i = blockIdx.x * 256 + threadIdx.x;
    float4 v = ((const float4*)A)[i];
    int row = (i * 4) >> 10, col = (i * 4) & 1023;
    __nv_bfloat16 hi[4], lo[4];
    split_bf16(v.x, hi[0], lo[0]);
    split_bf16(v.y, hi[1], lo[1]);
    split_bf16(v.z, hi[2], lo[2]);
    split_bf16(v.w, hi[3], lo[3]);
    *(ull*)&A2[(size_t)row * 2048 + col]        = *(ull*)hi;
    *(ull*)&A2[(size_t)row * 2048 + 1024 + col] = *(ull*)lo;
}

// ============================================================
// mma.sync bf16 GEMM, tripled-K hi/lo split (as R3).
// ============================================================
constexpr int GPITCH = 80;
constexpr int MAT_STAGE = 128 * GPITCH;
constexpr int STAGE_BYTES = 2 * MAT_STAGE;
constexpr int GSTG = 3;
constexpr int GEMM_SMEM = GSTG * STAGE_BYTES;
constexpr int NCHUNK = 96;

__device__ __forceinline__ void gemm_load_chunk(
    const __nv_bfloat16* __restrict__ A2, const __nv_bfloat16* __restrict__ B2,
    int m0, int n0, int c, uint32_t sbase, int tid)
{
    int s = c % GSTG;
    int kc = c * 32;
    int asrc = (kc >= 2048) ? (kc - 1024) : (kc & 1023);
    int bsrc = (kc >= 2048) ? (kc - 2048) : kc;
    uint32_t aSt = sbase + s * STAGE_BYTES;
    uint32_t bSt = aSt + MAT_STAGE;
    #pragma unroll
    for (int p = 0; p < 2; p++) {
        int e = tid + (p << 8);
        int r = e >> 2, cc = e & 3;
        cpasync16(aSt + r * GPITCH + cc * 16, A2 + (size_t)(m0 + r) * 2048 + asrc + cc * 8);
        cpasync16(bSt + r * GPITCH + cc * 16, B2 + (size_t)(n0 + r) * 2048 + bsrc + cc * 8);
    }
    cpcommit();
}

// mainloop shared by both epilogue variants
__device__ __forceinline__ void gemm_core(
    const __nv_bfloat16* A2, const __nv_bfloat16* B2,
    int m0, int n0, uint32_t sbase, int tid, int lane, int wm, int wn,
    float d[2][8][4])
{
    gemm_load_chunk(A2, B2, m0, n0, 0, sbase, tid);
    gemm_load_chunk(A2, B2, m0, n0, 1, sbase, tid);
    int lr = lane & 15;
    int lk = (lane >> 4) << 3;
    for (int c = 0; c < NCHUNK; c++) {
        cpwait<1>();
        __syncthreads();
        if (c + 2 < NCHUNK) gemm_load_chunk(A2, B2, m0, n0, c + 2, sbase, tid);
        else cpcommit();
        uint32_t aSt = sbase + (c % GSTG) * STAGE_BYTES;
        uint32_t bSt = aSt + MAT_STAGE;
        #pragma unroll
        for (int k16 = 0; k16 < 2; k16++) {
            uint32_t a[2][4], b[4][4];
            #pragma unroll
            for (int mt = 0; mt < 2; mt++)
                ldsm4(a[mt], aSt + (wm * 32 + mt * 16 + lr) * GPITCH + (k16 * 16 + lk) * 2);
            #pragma unroll
            for (int nt = 0; nt < 4; nt++)
                ldsm4(b[nt], bSt + (wn * 64 + nt * 16 + lr) * GPITCH + (k16 * 16 + lk) * 2);
            #pragma unroll
            for (int mt = 0; mt < 2; mt++)
                #pragma unroll
                for (int n8 = 0; n8 < 8; n8++) {
                    int nt = n8 >> 1, odd = n8 & 1;
                    mma16816(d[mt][n8], a[mt], b[nt][odd], b[nt][odd + 2]);
                }
        }
        __syncthreads();
    }
}

// QKV variant: writes split bf16 [B,NH,T,256] with scale folded in
__global__ void __launch_bounds__(256, 2) gemm_mma_qkv(
    const __nv_bfloat16* __restrict__ A2, const __nv_bfloat16* __restrict__ B2,
    __nv_bfloat16* __restrict__ Csplit, float scale)
{
    extern __shared__ char sm[];
    uint32_t sbase = s2u(sm);
    int tid = threadIdx.x, lane = tid & 31, warp = tid >> 5;
    int wm = warp >> 1, wn = warp & 1;
    int m0 = blockIdx.y << 7, n0 = blockIdx.x << 7;

    float d[2][8][4];
    #pragma unroll
    for (int i = 0; i < 2; i++)
        #pragma unroll
        for (int j = 0; j < 8; j++)
            #pragma unroll
            for (int q = 0; q < 4; q++) d[i][j][q] = 0.f;

    gemm_core(A2, B2, m0, n0, sbase, tid, lane, wm, wn, d);

    int mb = m0 + wm * 32 + (lane >> 2);
    int nb = n0 + wn * 64 + (lane & 3) * 2;
    #pragma unroll
    for (int mt = 0; mt < 2; mt++) {
        #pragma unroll
        for (int n8 = 0; n8 < 8; n8++) {
            int n = nb + n8 * 8;
            #pragma unroll
            for (int half = 0; half < 2; half++) {
                int m = mb + mt * 16 + half * 8;
                float c0 = d[mt][n8][half * 2] * scale, c1 = d[mt][n8][half * 2 + 1] * scale;
                int bI = m >> 11, t = m & 2047;
                int h = n >> 7, dd = n & 127;
                size_t base = ((size_t)(bI * NH + h) * TT + t) * 256 + dd;
                uint32_t hp, lp;
                pack_split2(c0, c1, hp, lp);
                *(uint32_t*)&Csplit[base]       = hp;
                *(uint32_t*)&Csplit[base + 128] = lp;
            }
        }
    }
}

// Output-projection variant: fp32 + residual
__global__ void __launch_bounds__(256, 2) gemm_mma_out(
    const __nv_bfloat16* __restrict__ A2, const __nv_bfloat16* __restrict__ B2,
    float* __restrict__ C, const float* __restrict__ R)
{
    extern __shared__ char sm[];
    uint32_t sbase = s2u(sm);
    int tid = threadIdx.x, lane = tid & 31, warp = tid >> 5;
    int wm = warp >> 1, wn = warp & 1;
    int m0 = blockIdx.y << 7, n0 = blockIdx.x << 7;

    float d[2][8][4];
    #pragma unroll
    for (int i = 0; i < 2; i++)
        #pragma unroll
        for (int j = 0; j < 8; j++)
            #pragma unroll
            for (int q = 0; q < 4; q++) d[i][j][q] = 0.f;

    gemm_core(A2, B2, m0, n0, sbase, tid, lane, wm, wn, d);

    int mb = m0 + wm * 32 + (lane >> 2);
    int nb = n0 + wn * 64 + (lane & 3) * 2;
    #pragma unroll
    for (int mt = 0; mt < 2; mt++) {
        #pragma unroll
        for (int n8 = 0; n8 < 8; n8++) {
            int n = nb + n8 * 8;
            #pragma unroll
            for (int half = 0; half < 2; half++) {
                int m = mb + mt * 16 + half * 8;
                size_t idx = (size_t)m * HD + n;
                float2 rr = *(const float2*)&R[idx];
                *(float2*)&C[idx] = make_float2(d[mt][n8][half * 2] + rr.x,
                                                d[mt][n8][half * 2 + 1] + rr.y);
            }
        }
    }
}

// ============================================================
// Flash attention on mma.sync, 3-term bf16 split, base-2 softmax.
// BM=BN=64, 8 warps (4m x 2n). Q pre-scaled by scale*log2(e).
// ============================================================
constexpr int FPB = 528;     // Q/K/V smem row pitch bytes (264 bf16)
constexpr int PPB = 144;     // P smem row pitch bytes (72 bf16)
constexpr int FL_Q  = 0;
constexpr int FL_K  = FL_Q + 64 * FPB;
constexpr int FL_V  = FL_K + 2 * 64 * FPB;
constexpr int FL_PH = FL_V + 2 * 64 * FPB;
constexpr int FL_PL = FL_PH + 64 * PPB;
constexpr int FL_PM = FL_PL + 64 * PPB;      // float pmax[2][64]
constexpr int FL_LS = FL_PM + 512;           // float lsum[2][64]
constexpr int FLASH_SMEM = FL_LS + 512;      // 188928 B

__global__ void __launch_bounds__(256, 1) flash_mma(
    const __nv_bfloat16* __restrict__ Q2, const __nv_bfloat16* __restrict__ K2,
    const __nv_bfloat16* __restrict__ V2, __nv_bfloat16* __restrict__ A2out)
{
    extern __shared__ char sm[];
    uint32_t sb = s2u(sm);
    int tid = threadIdx.x, lane = tid & 31, warp = tid >> 5;
    int wm = warp >> 1, wn = warp & 1;
    int qb = blockIdx.x, bh = blockIdx.y;
    int q0 = qb << 6;
    const __nv_bfloat16* qp = Q2 + (size_t)bh * TT * 256;
    const __nv_bfloat16* kp = K2 + (size_t)bh * TT * 256;
    const __nv_bfloat16* vp = V2 + (size_t)bh * TT * 256;
    float* pmaxS = (float*)(sm + FL_PM);
    float* lsumS = (float*)(sm + FL_LS);

    // prologue: Q tile + K/V block 0 in group 0
    #pragma unroll
    for (int p = 0; p < 8; p++) {
        int e = tid + (p << 8);
        int r = e >> 5, c = e & 31;
        cpasync16(sb + FL_Q + r * FPB + c * 16, qp + (size_t)(q0 + r) * 256 + c * 8);
        cpasync16(sb + FL_K + r * FPB + c * 16, kp + (size_t)r * 256 + c * 8);
        cpasync16(sb + FL_V + r * FPB + c * 16, vp + (size_t)r * 256 + c * 8);
    }
    cpcommit();

    float o[8][4];
    #pragma unroll
    for (int i = 0; i < 8; i++)
        #pragma unroll
        for (int j = 0; j < 4; j++) o[i][j] = 0.f;
    float m0r = -1e30f, m1r = -1e30f, l0r = 0.f, l1r = 0.f;

    int lr = lane & 15;
    int lk = (lane >> 4) << 3;
    int r0 = lane >> 2;                 // 0..7
    int rowA = wm * 16 + r0;            // rows rowA, rowA+8

    for (int kb = 0; kb <= qb; kb++) {
        int buf = kb & 1;
        __syncthreads();     // prior reads of buf^1 / P buffers complete
        if (kb < qb) {
            int kn0 = (kb + 1) << 6;
            uint32_t kD = sb + FL_K + (buf ^ 1) * 64 * FPB;
            uint32_t vD = sb + FL_V + (buf ^ 1) * 64 * FPB;
            #pragma unroll
            for (int p = 0; p < 8; p++) {
                int e = tid + (p << 8);
                int r = e >> 5, c = e & 31;
                cpasync16(kD + r * FPB + c * 16, kp + (size_t)(kn0 + r) * 256 + c * 8);
                cpasync16(vD + r * FPB + c * 16, vp + (size_t)(kn0 + r) * 256 + c * 8);
            }
        }
        cpcommit();
        cpwait<1>();
        __syncthreads();

        uint32_t qB = sb + FL_Q;
        uint32_t kB = sb + FL_K + buf * 64 * FPB;
        uint32_t vB = sb + FL_V + buf * 64 * FPB;

        // ---- S = Q K^T, 3-term ----
        float s[4][4];
        #pragma unroll
        for (int i = 0; i < 4; i++)
            #pragma unroll
            for (int j = 0; j < 4; j++) s[i][j] = 0.f;
        #pragma unroll
        for (int term = 0; term < 3; term++) {
            int ac = (term == 2) ? 128 : 0;
            int bc = (term == 1) ? 128 : 0;
            #pragma unroll
            for (int k16 = 0; k16 < 8; k16++) {
                uint32_t a[4], b0[4], b1[4];
                ldsm4(a,  qB + (wm * 16 + lr) * FPB + (ac + k16 * 16 + lk) * 2);
                ldsm4(b0, kB + (wn * 32 + lr) * FPB + (bc + k16 * 16 + lk) * 2);
                ldsm4(b1, kB + (wn * 32 + 16 + lr) * FPB + (bc + k16 * 16 + lk) * 2);
                mma16816(s[0], a, b0[0], b0[2]);
                mma16816(s[1], a, b0[1], b0[3]);
                mma16816(s[2], a, b1[0], b1[2]);
                mma16816(s[3], a, b1[1], b1[3]);
            }
        }
        // causal mask (diagonal block)
        if (kb == qb) {
            int rg0 = q0 + rowA;
            int cgb = (kb << 6) + wn * 32 + (lane & 3) * 2;
            #pragma unroll
            for (int n8 = 0; n8 < 4; n8++) {
                int cg = cgb + n8 * 8;
                if (cg     > rg0)     s[n8][0] = -1e30f;
                if (cg + 1 > rg0)     s[n8][1] = -1e30f;
                if (cg     > rg0 + 8) s[n8][2] = -1e30f;
                if (cg + 1 > rg0 + 8) s[n8][3] = -1e30f;
            }
        }
        // ---- partial row max -> smem ----
        float mx0 = -1e30f, mx1 = -1e30f;
        #pragma unroll
        for (int n8 = 0; n8 < 4; n8++) {
            mx0 = fmaxf(mx0, fmaxf(s[n8][0], s[n8][1]));
            mx1 = fmaxf(mx1, fmaxf(s[n8][2], s[n8][3]));
        }
        mx0 = fmaxf(mx0, __shfl_xor_sync(0xffffffffu, mx0, 1));
        mx0 = fmaxf(mx0, __shfl_xor_sync(0xffffffffu, mx0, 2));
        mx1 = fmaxf(mx1, __shfl_xor_sync(0xffffffffu, mx1, 1));
        mx1 = fmaxf(mx1, __shfl_xor_sync(0xffffffffu, mx1, 2));
        if ((lane & 3) == 0) {
            pmaxS[wn * 64 + rowA]     = mx0;
            pmaxS[wn * 64 + rowA + 8] = mx1;
        }
        __syncthreads();
        float mn0 = fmaxf(m0r, fmaxf(pmaxS[rowA],     pmaxS[64 + rowA]));
        float mn1 = fmaxf(m1r, fmaxf(pmaxS[rowA + 8], pmaxS[64 + rowA + 8]));
        float al0 = exp2f(m0r - mn0), al1 = exp2f(m1r - mn1);
        m0r = mn0; m1r = mn1;
        // exp (base-2), split P to smem, partial sums
        float ps0 = 0.f, ps1 = 0.f;
        #pragma unroll
        for (int n8 = 0; n8 < 4; n8++) {
            float e00 = exp2f(s[n8][0] - mn0);
            float e01 = exp2f(s[n8][1] - mn0);
            float e10 = exp2f(s[n8][2] - mn1);
            float e11 = exp2f(s[n8][3] - mn1);
            ps0 += e00 + e01;
            ps1 += e10 + e11;
            int col = wn * 32 + n8 * 8 + (lane & 3) * 2;
            uint32_t h0, lo0, h1, lo1;
            pack_split2(e00, e01, h0, lo0);
            pack_split2(e10, e11, h1, lo1);
            *(uint32_t*)(sm + FL_PH + rowA * PPB + col * 2)       = h0;
            *(uint32_t*)(sm + FL_PL + rowA * PPB + col * 2)       = lo0;
            *(uint32_t*)(sm + FL_PH + (rowA + 8) * PPB + col * 2) = h1;
            *(uint32_t*)(sm + FL_PL + (rowA + 8) * PPB + col * 2) = lo1;
        }
        ps0 += __shfl_xor_sync(0xffffffffu, ps0, 1);
        ps0 += __shfl_xor_sync(0xffffffffu, ps0, 2);
        ps1 += __shfl_xor_sync(0xffffffffu, ps1, 1);
        ps1 += __shfl_xor_sync(0xffffffffu, ps1, 2);
        if ((lane & 3) == 0) {
            lsumS[wn * 64 + rowA]     = ps0;
            lsumS[wn * 64 + rowA + 8] = ps1;
        }
        // rescale O (registers only)
        #pragma unroll
        for (int n8 = 0; n8 < 8; n8++) {
            o[n8][0] *= al0; o[n8][1] *= al0;
            o[n8][2] *= al1; o[n8][3] *= al1;
        }
        l0r *= al0; l1r *= al1;
        __syncthreads();
        l0r += lsumS[rowA]     + lsumS[64 + rowA];
        l1r += lsumS[rowA + 8] + lsumS[64 + rowA + 8];

        // ---- O += P V, 3 groups ----
        #pragma unroll
        for (int g = 0; g < 3; g++) {
            uint32_t pB = sb + ((g == 2) ? FL_PL : FL_PH);
            int vc = (g == 1) ? 128 : 0;
            #pragma unroll
            for (int k16 = 0; k16 < 4; k16++) {
                uint32_t a[4];
                ldsm4(a, pB + (wm * 16 + lr) * PPB + (k16 * 16 + lk) * 2);
                #pragma unroll
                for (int t16 = 0; t16 < 4; t16++) {
                    uint32_t bt[4];
                    ldsm4t(bt, vB + (k16 * 16 + lr) * FPB + (vc + wn * 64 + t16 * 16 + lk) * 2);
                    mma16816(o[t16 * 2],     a, bt[0], bt[1]);
                    mma16816(o[t16 * 2 + 1], a, bt[2], bt[3]);
                }
            }
        }
    }

    // epilogue: normalize, split, store [B,T,2048]
    float inv0 = 1.f / l0r, inv1 = 1.f / l1r;
    int b = bh >> 3, h = bh & 7;
    int t0 = q0 + rowA;
    #pragma unroll
    for (int n8 = 0; n8 < 8; n8++) {
        int d = wn * 64 + n8 * 8 + (lane & 3) * 2;
        size_t base0 = (size_t)(b * TT + t0) * 2048 + h * 128 + d;
        size_t base1 = base0 + 8 * 2048;
        uint32_t hp, lp;
        pack_split2(o[n8][0] * inv0, o[n8][1] * inv0, hp, lp);
        *(uint32_t*)&A2out[base0]        = hp;
        *(uint32_t*)&A2out[base0 + 1024] = lp;
        pack_split2(o[n8][2] * inv1, o[n8][3] * inv1, hp, lp);
        *(uint32_t*)&A2out[base1]        = hp;
        *(uint32_t*)&A2out[base1 + 1024] = lp;
    }
}

// ============================================================
// Launch
// ============================================================
extern "C" void kernel_launch(void* const* d_in, const int* in_sizes, int n_in,
                              void* d_out, int out_size)
{
    const float* x     = (const float*)d_in[0];
    const float* gamma = (const float*)d_in[1];
    const float* beta  = (const float*)d_in[2];
    const float* Wq    = (const float*)d_in[3];
    const float* Wk    = (const float*)d_in[4];
    const float* Wv    = (const float*)d_in[5];
    const float* Wo    = (const float*)d_in[6];
    float* out = (float*)d_out;

    __nv_bfloat16 *xn2, *w2, *q2, *k2, *v2, *attn2;
    cudaGetSymbolAddress((void**)&xn2,   g_xn2);
    cudaGetSymbolAddress((void**)&w2,    g_w2);
    cudaGetSymbolAddress((void**)&q2,    g_q2);
    cudaGetSymbolAddress((void**)&k2,    g_k2);
    cudaGetSymbolAddress((void**)&v2,    g_v2);
    cudaGetSymbolAddress((void**)&attn2, g_attn2);

    cudaFuncSetAttribute(gemm_mma_qkv, cudaFuncAttributeMaxDynamicSharedMemorySize, GEMM_SMEM);
    cudaFuncSetAttribute(gemm_mma_out, cudaFuncAttributeMaxDynamicSharedMemorySize, GEMM_SMEM);
    cudaFuncSetAttribute(flash_mma, cudaFuncAttributeMaxDynamicSharedMemorySize, FLASH_SMEM);

    ln_kernel<<<MM, 256>>>(x, gamma, beta, xn2);

    conv_split<<<1024, 256>>>(Wq, w2 + (size_t)0 * 1024 * 2048);
    conv_split<<<1024, 256>>>(Wk, w2 + (size_t)1 * 1024 * 2048);
    conv_split<<<1024, 256>>>(Wv, w2 + (size_t)2 * 1024 * 2048);
    conv_split<<<1024, 256>>>(Wo, w2 + (size_t)3 * 1024 * 2048);

    // scale*log2(e) folded into Q so softmax runs in base 2
    const float qscale = 0.08838834764831845f * 1.44269504088896341f;
    dim3 gg(HD / 128, MM / 128);   // (8, 64)
    gemm_mma_qkv<<<gg, 256, GEMM_SMEM>>>(xn2, w2 + (size_t)0 * 1024 * 2048, q2, qscale);
    gemm_mma_qkv<<<gg, 256, GEMM_SMEM>>>(xn2, w2 + (size_t)1 * 1024 * 2048, k2, 1.0f);
    gemm_mma_qkv<<<gg, 256, GEMM_SMEM>>>(xn2, w2 + (size_t)2 * 1024 * 2048, v2, 1.0f);

    flash_mma<<<dim3(TT / 64, BB * NH), 256, FLASH_SMEM>>>(q2, k2, v2, attn2);

    gemm_mma_out<<<gg, 256, GEMM_SMEM>>>(attn2, w2 + (size_t)3 * 1024 * 2048, out, x);
}

// round 6
// speedup vs baseline: 2.6196x; 2.6196x over previous
#include <cuda_runtime.h>
#include <cuda_fp16.h>
#include <math.h>
#include <cstdint>

constexpr int HD = 1024;
constexpr int NH = 8;
constexpr int DH = 128;
constexpr int BB = 4;
constexpr int TT = 2048;
constexpr int MM = BB * TT; // 8192

typedef unsigned long long ull;

// ---- scratch (allocation-free) ----
__device__ __half g_xn[MM * 1024];          // LN out fp16
__device__ __half g_w[4][1024 * 1024];      // weights fp16
__device__ __half g_q[32 * TT * 128];       // [B*NH][T][128], pre-scaled
__device__ __half g_k[32 * TT * 128];
__device__ __half g_v[32 * TT * 128];
__device__ __half g_attn[MM * 1024];        // attn fp16 [B,T,1024]

// ============================================================
// helpers
// ============================================================
__device__ __forceinline__ uint32_t s2u(const void* p) {
    uint32_t a;
    asm("{ .reg .u64 t; cvta.to.shared.u64 t, %1; cvt.u32.u64 %0, t; }" : "=r"(a) : "l"(p));
    return a;
}
__device__ __forceinline__ void cpasync16(uint32_t smem, const void* g) {
    asm volatile("cp.async.cg.shared.global [%0], [%1], 16;" :: "r"(smem), "l"(g));
}
__device__ __forceinline__ void cpcommit() { asm volatile("cp.async.commit_group;" ::: "memory"); }
template<int N> __device__ __forceinline__ void cpwait() {
    asm volatile("cp.async.wait_group %0;" :: "n"(N) : "memory");
}
__device__ __forceinline__ void ldsm4(uint32_t* r, uint32_t addr) {
    asm volatile("ldmatrix.sync.aligned.m8n8.x4.shared.b16 {%0,%1,%2,%3}, [%4];"
                 : "=r"(r[0]), "=r"(r[1]), "=r"(r[2]), "=r"(r[3]) : "r"(addr));
}
__device__ __forceinline__ void ldsm4t(uint32_t* r, uint32_t addr) {
    asm volatile("ldmatrix.sync.aligned.m8n8.x4.trans.shared.b16 {%0,%1,%2,%3}, [%4];"
                 : "=r"(r[0]), "=r"(r[1]), "=r"(r[2]), "=r"(r[3]) : "r"(addr));
}
__device__ __forceinline__ void mma16816(float* d, const uint32_t* a, uint32_t b0, uint32_t b1) {
    asm volatile("mma.sync.aligned.m16n8k16.row.col.f32.f16.f16.f32 "
                 "{%0,%1,%2,%3}, {%4,%5,%6,%7}, {%8,%9}, {%0,%1,%2,%3};"
                 : "+f"(d[0]), "+f"(d[1]), "+f"(d[2]), "+f"(d[3])
                 : "r"(a[0]), "r"(a[1]), "r"(a[2]), "r"(a[3]), "r"(b0), "r"(b1));
}
__device__ __forceinline__ uint32_t pack_h2(float a, float b) {
    __half2 h = __floats2half2_rn(a, b);
    return *(uint32_t*)&h;
}

// ============================================================
// LayerNorm -> fp16 [row][1024]
// ============================================================
__global__ void __launch_bounds__(256) ln_kernel(
    const float* __restrict__ x, const float* __restrict__ gamma,
    const float* __restrict__ beta, __half* __restrict__ xn)
{
    int row = blockIdx.x;
    int tid = threadIdx.x;
    const float* xr = x + (size_t)row * HD;
    float4 v = *(const float4*)&xr[tid * 4];
    float s  = v.x + v.y + v.z + v.w;
    float ss = v.x * v.x + v.y * v.y + v.z * v.z + v.w * v.w;
    #pragma unroll
    for (int o = 16; o; o >>= 1) {
        s  += __shfl_xor_sync(0xffffffffu, s,  o);
        ss += __shfl_xor_sync(0xffffffffu, ss, o);
    }
    __shared__ float rs[8], rss[8];
    if ((tid & 31) == 0) { rs[tid >> 5] = s; rss[tid >> 5] = ss; }
    __syncthreads();
    s = 0.f; ss = 0.f;
    #pragma unroll
    for (int i = 0; i < 8; i++) { s += rs[i]; ss += rss[i]; }
    float mu  = s * (1.0f / HD);
    float inv = rsqrtf(ss * (1.0f / HD) - mu * mu + 1e-5f);
    float4 g  = *(const float4*)&gamma[tid * 4];
    float4 be = *(const float4*)&beta[tid * 4];
    uint32_t p0 = pack_h2((v.x - mu) * inv * g.x + be.x, (v.y - mu) * inv * g.y + be.y);
    uint32_t p1 = pack_h2((v.z - mu) * inv * g.z + be.z, (v.w - mu) * inv * g.w + be.w);
    ull pk = (ull)p0 | ((ull)p1 << 32);
    *(ull*)&xn[(size_t)row * 1024 + tid * 4] = pk;
}

// fp32 -> fp16 (weights; layout unchanged)
__global__ void __launch_bounds__(256) conv_half(
    const float* __restrict__ A, __half* __restrict__ Ah)
{
    int i = blockIdx.x * 256 + threadIdx.x;
    float4 v = ((const float4*)A)[i];
    ull pk = (ull)pack_h2(v.x, v.y) | ((ull)pack_h2(v.z, v.w) << 32);
    *(ull*)&Ah[(size_t)i * 4] = pk;
}

// ============================================================
// mma.sync fp16 GEMM: C[m,n] = sum_k A[m,k]*W[n,k], fp32 accum.
// CTA 128x128, 8 warps (4m x 2n), warp 32x64, K-chunk 32, 3-stage cp.async.
// ============================================================
constexpr int GPITCH = 80;
constexpr int MAT_STAGE = 128 * GPITCH;
constexpr int STAGE_BYTES = 2 * MAT_STAGE;
constexpr int GSTG = 3;
constexpr int GEMM_SMEM = GSTG * STAGE_BYTES;
constexpr int NCHUNK = 32;   // 1024 / 32

__device__ __forceinline__ void gemm_load_chunk(
    const __half* __restrict__ A2, const __half* __restrict__ B2,
    int m0, int n0, int c, uint32_t sbase, int tid)
{
    int s = c % GSTG;
    int kc = c * 32;
    uint32_t aSt = sbase + s * STAGE_BYTES;
    uint32_t bSt = aSt + MAT_STAGE;
    #pragma unroll
    for (int p = 0; p < 2; p++) {
        int e = tid + (p << 8);
        int r = e >> 2, cc = e & 3;
        cpasync16(aSt + r * GPITCH + cc * 16, A2 + (size_t)(m0 + r) * 1024 + kc + cc * 8);
        cpasync16(bSt + r * GPITCH + cc * 16, B2 + (size_t)(n0 + r) * 1024 + kc + cc * 8);
    }
    cpcommit();
}

__device__ __forceinline__ void gemm_core(
    const __half* A2, const __half* B2,
    int m0, int n0, uint32_t sbase, int tid, int lane, int wm, int wn,
    float d[2][8][4])
{
    gemm_load_chunk(A2, B2, m0, n0, 0, sbase, tid);
    gemm_load_chunk(A2, B2, m0, n0, 1, sbase, tid);
    int lr = lane & 15;
    int lk = (lane >> 4) << 3;
    for (int c = 0; c < NCHUNK; c++) {
        cpwait<1>();
        __syncthreads();
        if (c + 2 < NCHUNK) gemm_load_chunk(A2, B2, m0, n0, c + 2, sbase, tid);
        else cpcommit();
        uint32_t aSt = sbase + (c % GSTG) * STAGE_BYTES;
        uint32_t bSt = aSt + MAT_STAGE;
        #pragma unroll
        for (int k16 = 0; k16 < 2; k16++) {
            uint32_t a[2][4], b[4][4];
            #pragma unroll
            for (int mt = 0; mt < 2; mt++)
                ldsm4(a[mt], aSt + (wm * 32 + mt * 16 + lr) * GPITCH + (k16 * 16 + lk) * 2);
            #pragma unroll
            for (int nt = 0; nt < 4; nt++)
                ldsm4(b[nt], bSt + (wn * 64 + nt * 16 + lr) * GPITCH + (k16 * 16 + lk) * 2);
            #pragma unroll
            for (int mt = 0; mt < 2; mt++)
                #pragma unroll
                for (int n8 = 0; n8 < 8; n8++) {
                    int nt = n8 >> 1, odd = n8 & 1;
                    mma16816(d[mt][n8], a[mt], b[nt][odd], b[nt][odd + 2]);
                }
        }
        __syncthreads();
    }
}

// QKV variant: fp16 out [B,NH,T,128], scale folded
__global__ void __launch_bounds__(256, 2) gemm_mma_qkv(
    const __half* __restrict__ A2, const __half* __restrict__ B2,
    __half* __restrict__ Ch, float scale)
{
    extern __shared__ char sm[];
    uint32_t sbase = s2u(sm);
    int tid = threadIdx.x, lane = tid & 31, warp = tid >> 5;
    int wm = warp >> 1, wn = warp & 1;
    int m0 = blockIdx.y << 7, n0 = blockIdx.x << 7;

    float d[2][8][4];
    #pragma unroll
    for (int i = 0; i < 2; i++)
        #pragma unroll
        for (int j = 0; j < 8; j++)
            #pragma unroll
            for (int q = 0; q < 4; q++) d[i][j][q] = 0.f;

    gemm_core(A2, B2, m0, n0, sbase, tid, lane, wm, wn, d);

    int mb = m0 + wm * 32 + (lane >> 2);
    int nb = n0 + wn * 64 + (lane & 3) * 2;
    #pragma unroll
    for (int mt = 0; mt < 2; mt++) {
        #pragma unroll
        for (int n8 = 0; n8 < 8; n8++) {
            int n = nb + n8 * 8;
            #pragma unroll
            for (int half = 0; half < 2; half++) {
                int m = mb + mt * 16 + half * 8;
                float c0 = d[mt][n8][half * 2] * scale, c1 = d[mt][n8][half * 2 + 1] * scale;
                int bI = m >> 11, t = m & 2047;
                int h = n >> 7, dd = n & 127;
                size_t base = ((size_t)(bI * NH + h) * TT + t) * 128 + dd;
                *(uint32_t*)&Ch[base] = pack_h2(c0, c1);
            }
        }
    }
}

// Output-projection variant: fp32 + residual
__global__ void __launch_bounds__(256, 2) gemm_mma_out(
    const __half* __restrict__ A2, const __half* __restrict__ B2,
    float* __restrict__ C, const float* __restrict__ R)
{
    extern __shared__ char sm[];
    uint32_t sbase = s2u(sm);
    int tid = threadIdx.x, lane = tid & 31, warp = tid >> 5;
    int wm = warp >> 1, wn = warp & 1;
    int m0 = blockIdx.y << 7, n0 = blockIdx.x << 7;

    float d[2][8][4];
    #pragma unroll
    for (int i = 0; i < 2; i++)
        #pragma unroll
        for (int j = 0; j < 8; j++)
            #pragma unroll
            for (int q = 0; q < 4; q++) d[i][j][q] = 0.f;

    gemm_core(A2, B2, m0, n0, sbase, tid, lane, wm, wn, d);

    int mb = m0 + wm * 32 + (lane >> 2);
    int nb = n0 + wn * 64 + (lane & 3) * 2;
    #pragma unroll
    for (int mt = 0; mt < 2; mt++) {
        #pragma unroll
        for (int n8 = 0; n8 < 8; n8++) {
            int n = nb + n8 * 8;
            #pragma unroll
            for (int half = 0; half < 2; half++) {
                int m = mb + mt * 16 + half * 8;
                size_t idx = (size_t)m * HD + n;
                float2 rr = *(const float2*)&R[idx];
                *(float2*)&C[idx] = make_float2(d[mt][n8][half * 2] + rr.x,
                                                d[mt][n8][half * 2 + 1] + rr.y);
            }
        }
    }
}

// ============================================================
// Flash attention on mma.sync fp16, base-2 softmax.
// BM=BN=64, D=128, 8 warps (4m x 2n). Q pre-scaled by scale*log2(e).
// ============================================================
constexpr int FPB = 272;     // Q/K/V smem row pitch bytes (128 halves + pad)
constexpr int PPB = 144;     // P smem row pitch bytes (64 halves + pad)
constexpr int FL_Q  = 0;
constexpr int FL_K  = FL_Q + 64 * FPB;        // 17408
constexpr int FL_V  = FL_K + 2 * 64 * FPB;    // 52224
constexpr int FL_P  = FL_V + 2 * 64 * FPB;    // 87040
constexpr int FL_PM = FL_P + 64 * PPB;        // 96256: float pmax[2][64]
constexpr int FL_LS = FL_PM + 512;            // float lsum[2][64]
constexpr int FLASH_SMEM = FL_LS + 512;       // 97280 B

__global__ void __launch_bounds__(256) flash_mma(
    const __half* __restrict__ Q2, const __half* __restrict__ K2,
    const __half* __restrict__ V2, __half* __restrict__ Aout)
{
    extern __shared__ char sm[];
    uint32_t sb = s2u(sm);
    int tid = threadIdx.x, lane = tid & 31, warp = tid >> 5;
    int wm = warp >> 1, wn = warp & 1;
    int qb = blockIdx.x, bh = blockIdx.y;
    int q0 = qb << 6;
    const __half* qp = Q2 + (size_t)bh * TT * 128;
    const __half* kp = K2 + (size_t)bh * TT * 128;
    const __half* vp = V2 + (size_t)bh * TT * 128;
    float* pmaxS = (float*)(sm + FL_PM);
    float* lsumS = (float*)(sm + FL_LS);

    // prologue: Q tile + K/V block 0 (64 rows x 16 x 16B each)
    #pragma unroll
    for (int p = 0; p < 4; p++) {
        int e = tid + (p << 8);
        int r = e >> 4, c = e & 15;
        cpasync16(sb + FL_Q + r * FPB + c * 16, qp + (size_t)(q0 + r) * 128 + c * 8);
        cpasync16(sb + FL_K + r * FPB + c * 16, kp + (size_t)r * 128 + c * 8);
        cpasync16(sb + FL_V + r * FPB + c * 16, vp + (size_t)r * 128 + c * 8);
    }
    cpcommit();

    float o[8][4];
    #pragma unroll
    for (int i = 0; i < 8; i++)
        #pragma unroll
        for (int j = 0; j < 4; j++) o[i][j] = 0.f;
    float m0r = -1e30f, m1r = -1e30f, l0r = 0.f, l1r = 0.f;

    int lr = lane & 15;
    int lk = (lane >> 4) << 3;
    int r0 = lane >> 2;
    int rowA = wm * 16 + r0;

    for (int kb = 0; kb <= qb; kb++) {
        int buf = kb & 1;
        __syncthreads();
        if (kb < qb) {
            int kn0 = (kb + 1) << 6;
            uint32_t kD = sb + FL_K + (buf ^ 1) * 64 * FPB;
            uint32_t vD = sb + FL_V + (buf ^ 1) * 64 * FPB;
            #pragma unroll
            for (int p = 0; p < 4; p++) {
                int e = tid + (p << 8);
                int r = e >> 4, c = e & 15;
                cpasync16(kD + r * FPB + c * 16, kp + (size_t)(kn0 + r) * 128 + c * 8);
                cpasync16(vD + r * FPB + c * 16, vp + (size_t)(kn0 + r) * 128 + c * 8);
            }
        }
        cpcommit();
        cpwait<1>();
        __syncthreads();

        uint32_t qB = sb + FL_Q;
        uint32_t kB = sb + FL_K + buf * 64 * FPB;
        uint32_t vB = sb + FL_V + buf * 64 * FPB;

        // ---- S = Q K^T ----
        float s[4][4];
        #pragma unroll
        for (int i = 0; i < 4; i++)
            #pragma unroll
            for (int j = 0; j < 4; j++) s[i][j] = 0.f;
        #pragma unroll
        for (int k16 = 0; k16 < 8; k16++) {
            uint32_t a[4], b0[4], b1[4];
            ldsm4(a,  qB + (wm * 16 + lr) * FPB + (k16 * 16 + lk) * 2);
            ldsm4(b0, kB + (wn * 32 + lr) * FPB + (k16 * 16 + lk) * 2);
            ldsm4(b1, kB + (wn * 32 + 16 + lr) * FPB + (k16 * 16 + lk) * 2);
            mma16816(s[0], a, b0[0], b0[2]);
            mma16816(s[1], a, b0[1], b0[3]);
            mma16816(s[2], a, b1[0], b1[2]);
            mma16816(s[3], a, b1[1], b1[3]);
        }
        // causal mask (diagonal block)
        if (kb == qb) {
            int rg0 = q0 + rowA;
            int cgb = (kb << 6) + wn * 32 + (lane & 3) * 2;
            #pragma unroll
            for (int n8 = 0; n8 < 4; n8++) {
                int cg = cgb + n8 * 8;
                if (cg     > rg0)     s[n8][0] = -1e30f;
                if (cg + 1 > rg0)     s[n8][1] = -1e30f;
                if (cg     > rg0 + 8) s[n8][2] = -1e30f;
                if (cg + 1 > rg0 + 8) s[n8][3] = -1e30f;
            }
        }
        // ---- partial row max ----
        float mx0 = -1e30f, mx1 = -1e30f;
        #pragma unroll
        for (int n8 = 0; n8 < 4; n8++) {
            mx0 = fmaxf(mx0, fmaxf(s[n8][0], s[n8][1]));
            mx1 = fmaxf(mx1, fmaxf(s[n8][2], s[n8][3]));
        }
        mx0 = fmaxf(mx0, __shfl_xor_sync(0xffffffffu, mx0, 1));
        mx0 = fmaxf(mx0, __shfl_xor_sync(0xffffffffu, mx0, 2));
        mx1 = fmaxf(mx1, __shfl_xor_sync(0xffffffffu, mx1, 1));
        mx1 = fmaxf(mx1, __shfl_xor_sync(0xffffffffu, mx1, 2));
        if ((lane & 3) == 0) {
            pmaxS[wn * 64 + rowA]     = mx0;
            pmaxS[wn * 64 + rowA + 8] = mx1;
        }
        __syncthreads();
        float mn0 = fmaxf(m0r, fmaxf(pmaxS[rowA],     pmaxS[64 + rowA]));
        float mn1 = fmaxf(m1r, fmaxf(pmaxS[rowA + 8], pmaxS[64 + rowA + 8]));
        float al0 = exp2f(m0r - mn0), al1 = exp2f(m1r - mn1);
        m0r = mn0; m1r = mn1;
        // exp (base-2), P -> smem fp16, partial sums
        float ps0 = 0.f, ps1 = 0.f;
        #pragma unroll
        for (int n8 = 0; n8 < 4; n8++) {
            float e00 = exp2f(s[n8][0] - mn0);
            float e01 = exp2f(s[n8][1] - mn0);
            float e10 = exp2f(s[n8][2] - mn1);
            float e11 = exp2f(s[n8][3] - mn1);
            ps0 += e00 + e01;
            ps1 += e10 + e11;
            int col = wn * 32 + n8 * 8 + (lane & 3) * 2;
            *(uint32_t*)(sm + FL_P + rowA * PPB + col * 2)       = pack_h2(e00, e01);
            *(uint32_t*)(sm + FL_P + (rowA + 8) * PPB + col * 2) = pack_h2(e10, e11);
        }
        ps0 += __shfl_xor_sync(0xffffffffu, ps0, 1);
        ps0 += __shfl_xor_sync(0xffffffffu, ps0, 2);
        ps1 += __shfl_xor_sync(0xffffffffu, ps1, 1);
        ps1 += __shfl_xor_sync(0xffffffffu, ps1, 2);
        if ((lane & 3) == 0) {
            lsumS[wn * 64 + rowA]     = ps0;
            lsumS[wn * 64 + rowA + 8] = ps1;
        }
        // rescale O
        #pragma unroll
        for (int n8 = 0; n8 < 8; n8++) {
            o[n8][0] *= al0; o[n8][1] *= al0;
            o[n8][2] *= al1; o[n8][3] *= al1;
        }
        l0r *= al0; l1r *= al1;
        __syncthreads();
        l0r += lsumS[rowA]     + lsumS[64 + rowA];
        l1r += lsumS[rowA + 8] + lsumS[64 + rowA + 8];

        // ---- O += P V ----
        #pragma unroll
        for (int k16 = 0; k16 < 4; k16++) {
            uint32_t a[4];
            ldsm4(a, sb + FL_P + (wm * 16 + lr) * PPB + (k16 * 16 + lk) * 2);
            #pragma unroll
            for (int t16 = 0; t16 < 4; t16++) {
                uint32_t bt[4];
                ldsm4t(bt, vB + (k16 * 16 + lr) * FPB + (wn * 64 + t16 * 16 + lk) * 2);
                mma16816(o[t16 * 2],     a, bt[0], bt[1]);
                mma16816(o[t16 * 2 + 1], a, bt[2], bt[3]);
            }
        }
    }

    // epilogue: normalize, fp16 store [B,T,1024]
    float inv0 = 1.f / l0r, inv1 = 1.f / l1r;
    int b = bh >> 3, h = bh & 7;
    int t0 = q0 + rowA;
    #pragma unroll
    for (int n8 = 0; n8 < 8; n8++) {
        int d = wn * 64 + n8 * 8 + (lane & 3) * 2;
        size_t base0 = (size_t)(b * TT + t0) * 1024 + h * 128 + d;
        size_t base1 = base0 + 8 * 1024;
        *(uint32_t*)&Aout[base0] = pack_h2(o[n8][0] * inv0, o[n8][1] * inv0);
        *(uint32_t*)&Aout[base1] = pack_h2(o[n8][2] * inv1, o[n8][3] * inv1);
    }
}

// ============================================================
// Launch
// ============================================================
extern "C" void kernel_launch(void* const* d_in, const int* in_sizes, int n_in,
                              void* d_out, int out_size)
{
    const float* x     = (const float*)d_in[0];
    const float* gamma = (const float*)d_in[1];
    const float* beta  = (const float*)d_in[2];
    const float* Wq    = (const float*)d_in[3];
    const float* Wk    = (const float*)d_in[4];
    const float* Wv    = (const float*)d_in[5];
    const float* Wo    = (const float*)d_in[6];
    float* out = (float*)d_out;

    __half *xn, *w, *q, *k, *v, *attn;
    cudaGetSymbolAddress((void**)&xn,   g_xn);
    cudaGetSymbolAddress((void**)&w,    g_w);
    cudaGetSymbolAddress((void**)&q,    g_q);
    cudaGetSymbolAddress((void**)&k,    g_k);
    cudaGetSymbolAddress((void**)&v,    g_v);
    cudaGetSymbolAddress((void**)&attn, g_attn);

    cudaFuncSetAttribute(gemm_mma_qkv, cudaFuncAttributeMaxDynamicSharedMemorySize, GEMM_SMEM);
    cudaFuncSetAttribute(gemm_mma_out, cudaFuncAttributeMaxDynamicSharedMemorySize, GEMM_SMEM);
    cudaFuncSetAttribute(flash_mma, cudaFuncAttributeMaxDynamicSharedMemorySize, FLASH_SMEM);

    ln_kernel<<<MM, 256>>>(x, gamma, beta, xn);

    conv_half<<<1024, 256>>>(Wq, w + (size_t)0 * 1024 * 1024);
    conv_half<<<1024, 256>>>(Wk, w + (size_t)1 * 1024 * 1024);
    conv_half<<<1024, 256>>>(Wv, w + (size_t)2 * 1024 * 1024);
    conv_half<<<1024, 256>>>(Wo, w + (size_t)3 * 1024 * 1024);

    // scale*log2(e) folded into Q so softmax runs in base 2
    const float qscale = 0.08838834764831845f * 1.44269504088896341f;
    dim3 gg(HD / 128, MM / 128);   // (8, 64)
    gemm_mma_qkv<<<gg, 256, GEMM_SMEM>>>(xn, w + (size_t)0 * 1024 * 1024, q, qscale);
    gemm_mma_qkv<<<gg, 256, GEMM_SMEM>>>(xn, w + (size_t)1 * 1024 * 1024, k, 1.0f);
    gemm_mma_qkv<<<gg, 256, GEMM_SMEM>>>(xn, w + (size_t)2 * 1024 * 1024, v, 1.0f);

    flash_mma<<<dim3(TT / 64, BB * NH), 256, FLASH_SMEM>>>(q, k, v, attn);

    gemm_mma_out<<<gg, 256, GEMM_SMEM>>>(attn, w + (size_t)3 * 1024 * 1024, out, x);
}

// round 7
// speedup vs baseline: 2.9712x; 1.1342x over previous
#include <cuda_runtime.h>
#include <cuda_fp16.h>
#include <math.h>
#include <cstdint>

constexpr int HD = 1024;
constexpr int NH = 8;
constexpr int DH = 128;
constexpr int BB = 4;
constexpr int TT = 2048;
constexpr int MM = BB * TT; // 8192

typedef unsigned long long ull;

// ---- scratch (allocation-free) ----
__device__ __half g_xn[MM * 1024];          // LN out fp16
__device__ __half g_w[4][1024 * 1024];      // weights fp16 (contiguous: q,k,v,o)
__device__ __half g_q[32 * TT * 128];       // [B*NH][T][128], pre-scaled
__device__ __half g_k[32 * TT * 128];
__device__ __half g_v[32 * TT * 128];
__device__ __half g_attn[MM * 1024];        // attn fp16 [B,T,1024]

// ============================================================
// helpers
// ============================================================
__device__ __forceinline__ uint32_t s2u(const void* p) {
    uint32_t a;
    asm("{ .reg .u64 t; cvta.to.shared.u64 t, %1; cvt.u32.u64 %0, t; }" : "=r"(a) : "l"(p));
    return a;
}
__device__ __forceinline__ void cpasync16(uint32_t smem, const void* g) {
    asm volatile("cp.async.cg.shared.global [%0], [%1], 16;" :: "r"(smem), "l"(g));
}
__device__ __forceinline__ void cpcommit() { asm volatile("cp.async.commit_group;" ::: "memory"); }
template<int N> __device__ __forceinline__ void cpwait() {
    asm volatile("cp.async.wait_group %0;" :: "n"(N) : "memory");
}
__device__ __forceinline__ void ldsm4(uint32_t* r, uint32_t addr) {
    asm volatile("ldmatrix.sync.aligned.m8n8.x4.shared.b16 {%0,%1,%2,%3}, [%4];"
                 : "=r"(r[0]), "=r"(r[1]), "=r"(r[2]), "=r"(r[3]) : "r"(addr));
}
__device__ __forceinline__ void ldsm4t(uint32_t* r, uint32_t addr) {
    asm volatile("ldmatrix.sync.aligned.m8n8.x4.trans.shared.b16 {%0,%1,%2,%3}, [%4];"
                 : "=r"(r[0]), "=r"(r[1]), "=r"(r[2]), "=r"(r[3]) : "r"(addr));
}
__device__ __forceinline__ void mma16816(float* d, const uint32_t* a, uint32_t b0, uint32_t b1) {
    asm volatile("mma.sync.aligned.m16n8k16.row.col.f32.f16.f16.f32 "
                 "{%0,%1,%2,%3}, {%4,%5,%6,%7}, {%8,%9}, {%0,%1,%2,%3};"
                 : "+f"(d[0]), "+f"(d[1]), "+f"(d[2]), "+f"(d[3])
                 : "r"(a[0]), "r"(a[1]), "r"(a[2]), "r"(a[3]), "r"(b0), "r"(b1));
}
__device__ __forceinline__ uint32_t pack_h2(float a, float b) {
    __half2 h = __floats2half2_rn(a, b);
    return *(uint32_t*)&h;
}

// ============================================================
// LayerNorm -> fp16 [row][1024]
// ============================================================
__global__ void __launch_bounds__(256) ln_kernel(
    const float* __restrict__ x, const float* __restrict__ gamma,
    const float* __restrict__ beta, __half* __restrict__ xn)
{
    int row = blockIdx.x;
    int tid = threadIdx.x;
    const float* xr = x + (size_t)row * HD;
    float4 v = *(const float4*)&xr[tid * 4];
    float s  = v.x + v.y + v.z + v.w;
    float ss = v.x * v.x + v.y * v.y + v.z * v.z + v.w * v.w;
    #pragma unroll
    for (int o = 16; o; o >>= 1) {
        s  += __shfl_xor_sync(0xffffffffu, s,  o);
        ss += __shfl_xor_sync(0xffffffffu, ss, o);
    }
    __shared__ float rs[8], rss[8];
    if ((tid & 31) == 0) { rs[tid >> 5] = s; rss[tid >> 5] = ss; }
    __syncthreads();
    s = 0.f; ss = 0.f;
    #pragma unroll
    for (int i = 0; i < 8; i++) { s += rs[i]; ss += rss[i]; }
    float mu  = s * (1.0f / HD);
    float inv = rsqrtf(ss * (1.0f / HD) - mu * mu + 1e-5f);
    float4 g  = *(const float4*)&gamma[tid * 4];
    float4 be = *(const float4*)&beta[tid * 4];
    uint32_t p0 = pack_h2((v.x - mu) * inv * g.x + be.x, (v.y - mu) * inv * g.y + be.y);
    uint32_t p1 = pack_h2((v.z - mu) * inv * g.z + be.z, (v.w - mu) * inv * g.w + be.w);
    ull pk = (ull)p0 | ((ull)p1 << 32);
    *(ull*)&xn[(size_t)row * 1024 + tid * 4] = pk;
}

// all four weights -> fp16 in one launch
__global__ void __launch_bounds__(256) conv_half4(
    const float* __restrict__ W0, const float* __restrict__ W1,
    const float* __restrict__ W2, const float* __restrict__ W3,
    __half* __restrict__ Wh)
{
    int sel = blockIdx.x >> 10;
    const float* src = (sel == 0) ? W0 : (sel == 1) ? W1 : (sel == 2) ? W2 : W3;
    int i = (blockIdx.x & 1023) * 256 + threadIdx.x;   // float4 index within one weight
    float4 v = ((const float4*)src)[i];
    ull pk = (ull)pack_h2(v.x, v.y) | ((ull)pack_h2(v.z, v.w) << 32);
    *(ull*)&Wh[((size_t)sel << 20) + (size_t)i * 4] = pk;
}

// ============================================================
// mma.sync fp16 GEMM core: CTA 128x128, 8 warps (4m x 2n),
// warp 32x64, K-chunk 32, 3-stage cp.async.
// ============================================================
constexpr int GPITCH = 80;
constexpr int MAT_STAGE = 128 * GPITCH;
constexpr int STAGE_BYTES = 2 * MAT_STAGE;
constexpr int GSTG = 3;
constexpr int GEMM_SMEM = GSTG * STAGE_BYTES;
constexpr int NCHUNK = 32;   // 1024 / 32

__device__ __forceinline__ void gemm_load_chunk(
    const __half* __restrict__ A2, const __half* __restrict__ B2,
    int m0, int n0, int c, uint32_t sbase, int tid)
{
    int s = c % GSTG;
    int kc = c * 32;
    uint32_t aSt = sbase + s * STAGE_BYTES;
    uint32_t bSt = aSt + MAT_STAGE;
    #pragma unroll
    for (int p = 0; p < 2; p++) {
        int e = tid + (p << 8);
        int r = e >> 2, cc = e & 3;
        cpasync16(aSt + r * GPITCH + cc * 16, A2 + (size_t)(m0 + r) * 1024 + kc + cc * 8);
        cpasync16(bSt + r * GPITCH + cc * 16, B2 + (size_t)(n0 + r) * 1024 + kc + cc * 8);
    }
    cpcommit();
}

__device__ __forceinline__ void gemm_core(
    const __half* A2, const __half* B2,
    int m0, int n0, uint32_t sbase, int tid, int lane, int wm, int wn,
    float d[2][8][4])
{
    gemm_load_chunk(A2, B2, m0, n0, 0, sbase, tid);
    gemm_load_chunk(A2, B2, m0, n0, 1, sbase, tid);
    int lr = lane & 15;
    int lk = (lane >> 4) << 3;
    for (int c = 0; c < NCHUNK; c++) {
        cpwait<1>();
        __syncthreads();
        if (c + 2 < NCHUNK) gemm_load_chunk(A2, B2, m0, n0, c + 2, sbase, tid);
        else cpcommit();
        uint32_t aSt = sbase + (c % GSTG) * STAGE_BYTES;
        uint32_t bSt = aSt + MAT_STAGE;
        #pragma unroll
        for (int k16 = 0; k16 < 2; k16++) {
            uint32_t a[2][4], b[4][4];
            #pragma unroll
            for (int mt = 0; mt < 2; mt++)
                ldsm4(a[mt], aSt + (wm * 32 + mt * 16 + lr) * GPITCH + (k16 * 16 + lk) * 2);
            #pragma unroll
            for (int nt = 0; nt < 4; nt++)
                ldsm4(b[nt], bSt + (wn * 64 + nt * 16 + lr) * GPITCH + (k16 * 16 + lk) * 2);
            #pragma unroll
            for (int mt = 0; mt < 2; mt++)
                #pragma unroll
                for (int n8 = 0; n8 < 8; n8++) {
                    int nt = n8 >> 1, odd = n8 & 1;
                    mma16816(d[mt][n8], a[mt], b[nt][odd], b[nt][odd + 2]);
                }
        }
        __syncthreads();
    }
}

// Fused QKV: B = concat(Wq,Wk,Wv) as 3072x1024; writes fp16 [B,NH,T,128]
__global__ void __launch_bounds__(256, 2) gemm_mma_qkv(
    const __half* __restrict__ A2, const __half* __restrict__ Ball,
    __half* __restrict__ Qo, __half* __restrict__ Ko, __half* __restrict__ Vo,
    float qscale)
{
    extern __shared__ char sm[];
    uint32_t sbase = s2u(sm);
    int tid = threadIdx.x, lane = tid & 31, warp = tid >> 5;
    int wm = warp >> 1, wn = warp & 1;
    int m0 = blockIdx.y << 7, n0 = blockIdx.x << 7;   // n0 in [0, 3072)
    int sel = n0 >> 10;
    __half* outp = (sel == 0) ? Qo : (sel == 1) ? Ko : Vo;
    float scale = (sel == 0) ? qscale : 1.0f;

    float d[2][8][4];
    #pragma unroll
    for (int i = 0; i < 2; i++)
        #pragma unroll
        for (int j = 0; j < 8; j++)
            #pragma unroll
            for (int q = 0; q < 4; q++) d[i][j][q] = 0.f;

    gemm_core(A2, Ball, m0, n0, sbase, tid, lane, wm, wn, d);

    int mb = m0 + wm * 32 + (lane >> 2);
    int nb = n0 + wn * 64 + (lane & 3) * 2;
    #pragma unroll
    for (int mt = 0; mt < 2; mt++) {
        #pragma unroll
        for (int n8 = 0; n8 < 8; n8++) {
            int n = nb + n8 * 8;
            #pragma unroll
            for (int half = 0; half < 2; half++) {
                int m = mb + mt * 16 + half * 8;
                float c0 = d[mt][n8][half * 2] * scale, c1 = d[mt][n8][half * 2 + 1] * scale;
                int bI = m >> 11, t = m & 2047;
                int h = (n >> 7) & 7, dd = n & 127;
                size_t base = ((size_t)(bI * NH + h) * TT + t) * 128 + dd;
                *(uint32_t*)&outp[base] = pack_h2(c0, c1);
            }
        }
    }
}

// Output-projection: fp32 + residual
__global__ void __launch_bounds__(256, 2) gemm_mma_out(
    const __half* __restrict__ A2, const __half* __restrict__ B2,
    float* __restrict__ C, const float* __restrict__ R)
{
    extern __shared__ char sm[];
    uint32_t sbase = s2u(sm);
    int tid = threadIdx.x, lane = tid & 31, warp = tid >> 5;
    int wm = warp >> 1, wn = warp & 1;
    int m0 = blockIdx.y << 7, n0 = blockIdx.x << 7;

    float d[2][8][4];
    #pragma unroll
    for (int i = 0; i < 2; i++)
        #pragma unroll
        for (int j = 0; j < 8; j++)
            #pragma unroll
            for (int q = 0; q < 4; q++) d[i][j][q] = 0.f;

    gemm_core(A2, B2, m0, n0, sbase, tid, lane, wm, wn, d);

    int mb = m0 + wm * 32 + (lane >> 2);
    int nb = n0 + wn * 64 + (lane & 3) * 2;
    #pragma unroll
    for (int mt = 0; mt < 2; mt++) {
        #pragma unroll
        for (int n8 = 0; n8 < 8; n8++) {
            int n = nb + n8 * 8;
            #pragma unroll
            for (int half = 0; half < 2; half++) {
                int m = mb + mt * 16 + half * 8;
                size_t idx = (size_t)m * HD + n;
                float2 rr = *(const float2*)&R[idx];
                *(float2*)&C[idx] = make_float2(d[mt][n8][half * 2] + rr.x,
                                                d[mt][n8][half * 2 + 1] + rr.y);
            }
        }
    }
}

// ============================================================
// Flash attention, FA2 style: BM=128, BN=64, 8 warps x 16 rows.
// Q in registers; softmax warp-local; S-accum fragments reused
// directly as A operands of P@V (no P smem round trip).
// Q pre-scaled by scale*log2(e); base-2 softmax.
// ============================================================
constexpr int FPB = 272;                      // row pitch bytes (128 halves + pad)
constexpr int FL_Q = 0;                       // 128 x FPB = 34816
constexpr int FL_K = FL_Q + 128 * FPB;        // 2 bufs x 64 x FPB
constexpr int FL_V = FL_K + 2 * 64 * FPB;
constexpr int FLASH_SMEM = FL_V + 2 * 64 * FPB;   // 104448 B

__global__ void __launch_bounds__(256) flash_mma(
    const __half* __restrict__ Q2, const __half* __restrict__ K2,
    const __half* __restrict__ V2, __half* __restrict__ Aout)
{
    extern __shared__ char sm[];
    uint32_t sb = s2u(sm);
    int tid = threadIdx.x, lane = tid & 31, w = tid >> 5;
    int g = lane >> 2, tig = lane & 3;
    int qb = gridDim.x - 1 - blockIdx.x;      // largest tiles scheduled first
    int bh = blockIdx.y;
    int q0 = qb << 7;
    const __half* qp = Q2 + (size_t)bh * TT * 128;
    const __half* kp = K2 + (size_t)bh * TT * 128;
    const __half* vp = V2 + (size_t)bh * TT * 128;

    // prologue: Q tile (128 rows) + K/V block 0 (64 rows each), one group
    #pragma unroll
    for (int p = 0; p < 8; p++) {
        int e = tid + (p << 8);
        int r = e >> 4, c = e & 15;
        cpasync16(sb + FL_Q + r * FPB + c * 16, qp + (size_t)(q0 + r) * 128 + c * 8);
    }
    #pragma unroll
    for (int p = 0; p < 4; p++) {
        int e = tid + (p << 8);
        int r = e >> 4, c = e & 15;
        cpasync16(sb + FL_K + r * FPB + c * 16, kp + (size_t)r * 128 + c * 8);
        cpasync16(sb + FL_V + r * FPB + c * 16, vp + (size_t)r * 128 + c * 8);
    }
    cpcommit();
    cpwait<0>();
    __syncthreads();

    int lr = lane & 15;
    int lk = (lane >> 4) << 3;

    // Q -> registers (A fragments for all 8 k16 chunks)
    uint32_t qf[8][4];
    #pragma unroll
    for (int c8 = 0; c8 < 8; c8++)
        ldsm4(qf[c8], sb + FL_Q + (w * 16 + lr) * FPB + (c8 * 16 + lk) * 2);

    float o[16][4];
    #pragma unroll
    for (int i = 0; i < 16; i++)
        #pragma unroll
        for (int j = 0; j < 4; j++) o[i][j] = 0.f;
    float m0r = -1e30f, m1r = -1e30f, l0r = 0.f, l1r = 0.f;

    int nkb = 2 * qb + 2;
    for (int kb = 0; kb < nkb; kb++) {
        int buf = kb & 1;
        __syncthreads();   // all warps finished reading buf^1 (step kb-2)
        if (kb + 1 < nkb) {
            int kn0 = (kb + 1) << 6;
            uint32_t kD = sb + FL_K + (buf ^ 1) * 64 * FPB;
            uint32_t vD = sb + FL_V + (buf ^ 1) * 64 * FPB;
            #pragma unroll
            for (int p = 0; p < 4; p++) {
                int e = tid + (p << 8);
                int r = e >> 4, c = e & 15;
                cpasync16(kD + r * FPB + c * 16, kp + (size_t)(kn0 + r) * 128 + c * 8);
                cpasync16(vD + r * FPB + c * 16, vp + (size_t)(kn0 + r) * 128 + c * 8);
            }
        }
        cpcommit();
        cpwait<1>();
        __syncthreads();

        uint32_t kB = sb + FL_K + buf * 64 * FPB;
        uint32_t vB = sb + FL_V + buf * 64 * FPB;

        // ---- S = Q K^T : warp computes 16x64 ----
        float s[8][4];
        #pragma unroll
        for (int i = 0; i < 8; i++)
            #pragma unroll
            for (int j = 0; j < 4; j++) s[i][j] = 0.f;
        #pragma unroll
        for (int k16 = 0; k16 < 8; k16++) {
            uint32_t b[4][4];
            #pragma unroll
            for (int t = 0; t < 4; t++)
                ldsm4(b[t], kB + (t * 16 + lr) * FPB + (k16 * 16 + lk) * 2);
            #pragma unroll
            for (int j = 0; j < 8; j++)
                mma16816(s[j], qf[k16], b[j >> 1][j & 1], b[j >> 1][(j & 1) + 2]);
        }

        // causal mask: only the last two k-blocks intersect the diagonal
        if (kb >= 2 * qb) {
            int rg0 = q0 + w * 16 + g;
            int rg1 = rg0 + 8;
            int cgb = (kb << 6) + tig * 2;
            #pragma unroll
            for (int j = 0; j < 8; j++) {
                int cg = cgb + j * 8;
                if (cg     > rg0) s[j][0] = -1e30f;
                if (cg + 1 > rg0) s[j][1] = -1e30f;
                if (cg     > rg1) s[j][2] = -1e30f;
                if (cg + 1 > rg1) s[j][3] = -1e30f;
            }
        }

        // ---- warp-local softmax (rows g, g+8; 4 threads per row) ----
        float mx0 = -1e30f, mx1 = -1e30f;
        #pragma unroll
        for (int j = 0; j < 8; j++) {
            mx0 = fmaxf(mx0, fmaxf(s[j][0], s[j][1]));
            mx1 = fmaxf(mx1, fmaxf(s[j][2], s[j][3]));
        }
        mx0 = fmaxf(mx0, __shfl_xor_sync(0xffffffffu, mx0, 1));
        mx0 = fmaxf(mx0, __shfl_xor_sync(0xffffffffu, mx0, 2));
        mx1 = fmaxf(mx1, __shfl_xor_sync(0xffffffffu, mx1, 1));
        mx1 = fmaxf(mx1, __shfl_xor_sync(0xffffffffu, mx1, 2));
        float mn0 = fmaxf(m0r, mx0), mn1 = fmaxf(m1r, mx1);
        float al0 = exp2f(m0r - mn0), al1 = exp2f(m1r - mn1);
        m0r = mn0; m1r = mn1;

        float ps0 = 0.f, ps1 = 0.f;
        #pragma unroll
        for (int j = 0; j < 8; j++) {
            s[j][0] = exp2f(s[j][0] - mn0);
            s[j][1] = exp2f(s[j][1] - mn0);
            s[j][2] = exp2f(s[j][2] - mn1);
            s[j][3] = exp2f(s[j][3] - mn1);
            ps0 += s[j][0] + s[j][1];
            ps1 += s[j][2] + s[j][3];
        }
        ps0 += __shfl_xor_sync(0xffffffffu, ps0, 1);
        ps0 += __shfl_xor_sync(0xffffffffu, ps0, 2);
        ps1 += __shfl_xor_sync(0xffffffffu, ps1, 1);
        ps1 += __shfl_xor_sync(0xffffffffu, ps1, 2);
        l0r = l0r * al0 + ps0;
        l1r = l1r * al1 + ps1;

        // rescale O
        #pragma unroll
        for (int j = 0; j < 16; j++) {
            o[j][0] *= al0; o[j][1] *= al0;
            o[j][2] *= al1; o[j][3] *= al1;
        }

        // P fragments straight from S accumulators (C layout == A layout)
        uint32_t pa[4][4];
        #pragma unroll
        for (int c = 0; c < 4; c++) {
            pa[c][0] = pack_h2(s[2 * c][0],     s[2 * c][1]);
            pa[c][1] = pack_h2(s[2 * c][2],     s[2 * c][3]);
            pa[c][2] = pack_h2(s[2 * c + 1][0], s[2 * c + 1][1]);
            pa[c][3] = pack_h2(s[2 * c + 1][2], s[2 * c + 1][3]);
        }

        // ---- O += P V : warp computes 16x128 ----
        #pragma unroll
        for (int c = 0; c < 4; c++) {
            #pragma unroll
            for (int j = 0; j < 8; j++) {
                uint32_t bt[4];
                ldsm4t(bt, vB + (c * 16 + lr) * FPB + (j * 16 + lk) * 2);
                mma16816(o[2 * j],     pa[c], bt[0], bt[1]);
                mma16816(o[2 * j + 1], pa[c], bt[2], bt[3]);
            }
        }
    }

    // epilogue: normalize, fp16 store [B,T,1024]
    float inv0 = 1.f / l0r, inv1 = 1.f / l1r;
    int b = bh >> 3, h = bh & 7;
    int t0 = q0 + w * 16 + g;
    #pragma unroll
    for (int j = 0; j < 16; j++) {
        int d = j * 8 + tig * 2;
        size_t base0 = (size_t)(b * TT + t0) * 1024 + h * 128 + d;
        size_t base1 = base0 + 8 * 1024;
        *(uint32_t*)&Aout[base0] = pack_h2(o[j][0] * inv0, o[j][1] * inv0);
        *(uint32_t*)&Aout[base1] = pack_h2(o[j][2] * inv1, o[j][3] * inv1);
    }
}

// ============================================================
// Launch
// ============================================================
extern "C" void kernel_launch(void* const* d_in, const int* in_sizes, int n_in,
                              void* d_out, int out_size)
{
    const float* x     = (const float*)d_in[0];
    const float* gamma = (const float*)d_in[1];
    const float* beta  = (const float*)d_in[2];
    const float* Wq    = (const float*)d_in[3];
    const float* Wk    = (const float*)d_in[4];
    const float* Wv    = (const float*)d_in[5];
    const float* Wo    = (const float*)d_in[6];
    float* out = (float*)d_out;

    __half *xn, *w, *q, *k, *v, *attn;
    cudaGetSymbolAddress((void**)&xn,   g_xn);
    cudaGetSymbolAddress((void**)&w,    g_w);
    cudaGetSymbolAddress((void**)&q,    g_q);
    cudaGetSymbolAddress((void**)&k,    g_k);
    cudaGetSymbolAddress((void**)&v,    g_v);
    cudaGetSymbolAddress((void**)&attn, g_attn);

    cudaFuncSetAttribute(gemm_mma_qkv, cudaFuncAttributeMaxDynamicSharedMemorySize, GEMM_SMEM);
    cudaFuncSetAttribute(gemm_mma_out, cudaFuncAttributeMaxDynamicSharedMemorySize, GEMM_SMEM);
    cudaFuncSetAttribute(flash_mma, cudaFuncAttributeMaxDynamicSharedMemorySize, FLASH_SMEM);

    ln_kernel<<<MM, 256>>>(x, gamma, beta, xn);
    conv_half4<<<4096, 256>>>(Wq, Wk, Wv, Wo, w);

    // scale*log2(e) folded into Q so softmax runs in base 2
    const float qscale = 0.08838834764831845f * 1.44269504088896341f;
    gemm_mma_qkv<<<dim3(24, 64), 256, GEMM_SMEM>>>(xn, w, q, k, v, qscale);

    flash_mma<<<dim3(TT / 128, BB * NH), 256, FLASH_SMEM>>>(q, k, v, attn);

    gemm_mma_out<<<dim3(8, 64), 256, GEMM_SMEM>>>(attn, w + ((size_t)3 << 20), out, x);
}